// round 2
// baseline (speedup 1.0000x reference)
#include <cuda_runtime.h>
#include <math.h>
#include <stdint.h>

// Problem constants
#define Tt   4
#define Bb   4
#define Nn   16384
#define KALLc 4
#define Ff   16384
#define ORD  3
#define DINc 4
#define Hh   64
#define NHc  4
#define HDc  16
#define DEc  4
#define DOUTc 64
#define N0c  4096

#define TBc  (Tt*Bb)        // 16
#define BNc  (Bb*Nn)        // 65536
#define TBNc (TBc*Nn)       // 262144
#define H3c  (3*Hh)         // 192

// Output layout (concatenation of reference outputs, row-major flatten):
//   h_fin  [B,N,H]     : 4194304
//   h_global [B,K,DOUT]: 1024
//   logit  [T,B,N]     : 262144
//   value  [T,B]       : 16
#define OFF_HG    4194304
#define OFF_LOGIT (OFF_HG + 1024)
#define OFF_VAL   (OFF_LOGIT + 262144)

// Scratch (device globals — no allocation allowed in kernel_launch)
__device__ float g_qkv[TBNc * H3c];   // [T,B,N,192]  q|k|v per node  (192 MiB)
__device__ float g_yo [TBNc * Hh];    // [T,B,N,64]   scatter-sum of attention outputs o
__device__ float g_yg [TBc * KALLc * Hh]; // per-(t,b,kall) sum of y (for y_global)
__device__ int   g_cnt[Nn];           // per-node reference count

__device__ __forceinline__ float sigmoidf_(float v) { return 1.f / (1.f + expf(-v)); }
__device__ __forceinline__ void fma4_(float4& a, float s, float4 w) {
    a.x += s * w.x; a.y += s * w.y; a.z += s * w.z; a.w += s * w.w;
}

// ---------------------------------------------------------------------------
// Histogram of indices -> g_cnt
// ---------------------------------------------------------------------------
__global__ void k_count(const int* __restrict__ indices) {
    int i = blockIdx.x * 256 + threadIdx.x;
    if (i < Ff * ORD) atomicAdd(&g_cnt[indices[i]], 1);
}

// ---------------------------------------------------------------------------
// Fused GRU scan (T=4) + per-step QKV projection. One thread per (b,n) node.
// h[64] lives in registers; all weights in shared (broadcast reads).
// Writes g_qkv for every step and h_fin to output.
// ---------------------------------------------------------------------------
__global__ __launch_bounds__(128)
void k_gru_qkv(const float* __restrict__ h0, const float* __restrict__ x,
               const uint32_t* __restrict__ dones,   // bool widened to 4-byte (int32/f32)
               const float* __restrict__ Wi, const float* __restrict__ bi,
               const float* __restrict__ Wh, const float* __restrict__ bhn,
               const float* __restrict__ Wq, const float* __restrict__ bq,
               const float* __restrict__ Wk, const float* __restrict__ bk,
               const float* __restrict__ Wv, const float* __restrict__ bv,
               float* __restrict__ hfin_out)
{
    extern __shared__ float smem[];
    float* sWh   = smem;              // 64*192 = 12288
    float* sWi   = sWh + 12288;       // 4*192  = 768
    float* sWqkv = sWi + 768;         // 64*192 = 12288
    float* sbi   = sWqkv + 12288;     // 192
    float* sbqkv = sbi + 192;         // 192
    float* sbhn  = sbqkv + 192;       // 64

    for (int i = threadIdx.x; i < 12288; i += 128) sWh[i] = Wh[i];
    for (int i = threadIdx.x; i < 768;   i += 128) sWi[i] = Wi[i];
    for (int i = threadIdx.x; i < 12288; i += 128) {
        int j = i / 192, e = i % 192;
        sWqkv[i] = (e < 64) ? Wq[j*64 + e] : (e < 128) ? Wk[j*64 + e - 64] : Wv[j*64 + e - 128];
    }
    for (int i = threadIdx.x; i < 192; i += 128) sbi[i] = bi[i];
    for (int i = threadIdx.x; i < 192; i += 128)
        sbqkv[i] = (i < 64) ? bq[i] : (i < 128) ? bk[i - 64] : bv[i - 128];
    for (int i = threadIdx.x; i < 64; i += 128) sbhn[i] = bhn[i];
    __syncthreads();

    const float4* sWh4   = (const float4*)sWh;
    const float4* sWi4   = (const float4*)sWi;
    const float4* sWqkv4 = (const float4*)sWqkv;
    const float4* sbi4   = (const float4*)sbi;
    const float4* sbqkv4 = (const float4*)sbqkv;
    const float4* sbhn4  = (const float4*)sbhn;

    int gid = blockIdx.x * 128 + threadIdx.x;   // 0 .. 65535 == b*N + n
    int b = gid >> 14;

    float h[64];
    {
        const float4* h04 = (const float4*)(h0 + (size_t)gid * 64);
        #pragma unroll
        for (int j = 0; j < 16; j++) {
            float4 v = h04[j];
            h[4*j] = v.x; h[4*j+1] = v.y; h[4*j+2] = v.z; h[4*j+3] = v.w;
        }
    }

    #pragma unroll 1
    for (int t = 0; t < Tt; t++) {
        if (dones[t * Bb + b] != 0u) {
            #pragma unroll
            for (int j = 0; j < 64; j++) h[j] = 0.f;
        }
        float4 xt4 = ((const float4*)x)[(size_t)t * BNc + gid];
        float xt[4] = {xt4.x, xt4.y, xt4.z, xt4.w};

        float hn[64];
        #pragma unroll
        for (int kk = 0; kk < 16; kk++) {
            float4 ar = {0,0,0,0}, az = {0,0,0,0}, an = {0,0,0,0};
            #pragma unroll
            for (int j = 0; j < 64; j++) {
                float hj = h[j];
                fma4_(ar, hj, sWh4[j*48 + kk]);
                fma4_(az, hj, sWh4[j*48 + 16 + kk]);
                fma4_(an, hj, sWh4[j*48 + 32 + kk]);
            }
            float4 gr = sbi4[kk], gz = sbi4[16 + kk], gn = sbi4[32 + kk];
            #pragma unroll
            for (int d = 0; d < 4; d++) {
                float xd = xt[d];
                fma4_(gr, xd, sWi4[d*48 + kk]);
                fma4_(gz, xd, sWi4[d*48 + 16 + kk]);
                fma4_(gn, xd, sWi4[d*48 + 32 + kk]);
            }
            float4 bn4 = sbhn4[kk];
            {
                float r = sigmoidf_(gr.x + ar.x);
                float z = sigmoidf_(gz.x + az.x);
                float nv = tanhf(gn.x + r * (an.x + bn4.x));
                hn[4*kk+0] = (1.f - z) * nv + z * h[4*kk+0];
            }
            {
                float r = sigmoidf_(gr.y + ar.y);
                float z = sigmoidf_(gz.y + az.y);
                float nv = tanhf(gn.y + r * (an.y + bn4.y));
                hn[4*kk+1] = (1.f - z) * nv + z * h[4*kk+1];
            }
            {
                float r = sigmoidf_(gr.z + ar.z);
                float z = sigmoidf_(gz.z + az.z);
                float nv = tanhf(gn.z + r * (an.z + bn4.z));
                hn[4*kk+2] = (1.f - z) * nv + z * h[4*kk+2];
            }
            {
                float r = sigmoidf_(gr.w + ar.w);
                float z = sigmoidf_(gz.w + az.w);
                float nv = tanhf(gn.w + r * (an.w + bn4.w));
                hn[4*kk+3] = (1.f - z) * nv + z * h[4*kk+3];
            }
        }
        #pragma unroll
        for (int j = 0; j < 64; j++) h[j] = hn[j];

        // QKV projection of the new hidden state
        float4* out = (float4*)(g_qkv + ((size_t)t * BNc + gid) * H3c);
        #pragma unroll 1
        for (int kk = 0; kk < 48; kk++) {
            float4 acc = sbqkv4[kk];
            #pragma unroll
            for (int j = 0; j < 64; j++) fma4_(acc, h[j], sWqkv4[j*48 + kk]);
            out[kk] = acc;
        }
    }

    float4* ho = (float4*)(hfin_out + (size_t)gid * 64);
    #pragma unroll
    for (int j = 0; j < 16; j++) {
        float4 v = {h[4*j], h[4*j+1], h[4*j+2], h[4*j+3]};
        ho[j] = v;
    }
}

// ---------------------------------------------------------------------------
// Attention per (t,b,f): gather 3 qkv rows, 4-head softmax over 3x3,
// produce o[3][64], scatter-add into g_yo with float4 atomics.
// One warp per instance; blocks ordered so same (t,b) is adjacent (L2 reuse).
// ---------------------------------------------------------------------------
__global__ __launch_bounds__(256)
void k_attn(const int* __restrict__ indices)
{
    __shared__ __align__(16) float sR[8][3][192];
    __shared__ __align__(16) float sO[8][3][64];

    int warp = threadIdx.x >> 5, lane = threadIdx.x & 31;
    int inst = blockIdx.x * 8 + warp;      // = tb*F + f
    int tb = inst >> 14;
    int f  = inst & 16383;

    int idx0 = __ldg(&indices[f*3 + 0]);
    int idx1 = __ldg(&indices[f*3 + 1]);
    int idx2 = __ldg(&indices[f*3 + 2]);
    int idx[3] = {idx0, idx1, idx2};

    const float* base = g_qkv + (size_t)tb * Nn * H3c;
    #pragma unroll
    for (int k = 0; k < 3; k++) {
        const float* row = base + (size_t)idx[k] * H3c;
        #pragma unroll
        for (int u = 0; u < 6; u++) sR[warp][k][u*32 + lane] = row[u*32 + lane];
    }
    __syncwarp();

    if (lane < 12) {
        int qr = lane >> 2;          // 0..2
        int hh = lane & 3;           // 0..3
        const float* q = &sR[warp][qr][hh * 16];
        float l[3];
        #pragma unroll
        for (int kr = 0; kr < 3; kr++) {
            const float* kv = &sR[warp][kr][64 + hh * 16];
            float s = 0.f;
            #pragma unroll
            for (int d = 0; d < 16; d++) s += q[d] * kv[d];
            l[kr] = s * 0.25f;       // scale = 1/sqrt(16)
        }
        float m = fmaxf(l[0], fmaxf(l[1], l[2]));
        float e0 = expf(l[0] - m), e1 = expf(l[1] - m), e2 = expf(l[2] - m);
        float inv = 1.f / (e0 + e1 + e2);
        e0 *= inv; e1 *= inv; e2 *= inv;
        const float* v0 = &sR[warp][0][128 + hh * 16];
        const float* v1 = &sR[warp][1][128 + hh * 16];
        const float* v2 = &sR[warp][2][128 + hh * 16];
        #pragma unroll
        for (int d = 0; d < 16; d++)
            sO[warp][qr][hh*16 + d] = e0 * v0[d] + e1 * v1[d] + e2 * v2[d];
    }
    __syncwarp();

    float4* yo = (float4*)g_yo + (size_t)tb * Nn * 16;
    if (lane < 16) {
        #pragma unroll
        for (int k = 0; k < 3; k++) {
            float4 v = ((const float4*)sO[warp][k])[lane];
            atomicAdd(&yo[(size_t)idx[k] * 16 + lane], v);   // sm_90+ vector atomic
        }
    }
}

// ---------------------------------------------------------------------------
// Post: per node-row y = (yo@Wo + cnt*bo)/nnz; accumulate y_global partials;
// logit = relu([y,extra]@W1 + b1)@W2 + b2. One warp per row, 8 rows/block.
// ---------------------------------------------------------------------------
__global__ __launch_bounds__(256)
void k_post(const float* __restrict__ nnz, const float* __restrict__ extra,
            const float* __restrict__ Wo, const float* __restrict__ bo,
            const float* __restrict__ W1, const float* __restrict__ b1,
            const float* __restrict__ W2, const float* __restrict__ b2,
            float* __restrict__ logit_out)
{
    __shared__ float sWo[64*64];
    __shared__ float sW1[68*64];
    __shared__ float sbo[64], sb1[64], sW2[64];
    __shared__ float sY[8][64];
    __shared__ float sZ[8][72];
    __shared__ float sAcc[64];
    __shared__ float sb2;

    int tid = threadIdx.x;
    for (int i = tid; i < 64*64; i += 256) sWo[i] = Wo[i];
    for (int i = tid; i < 68*64; i += 256) sW1[i] = W1[i];
    if (tid < 64) { sbo[tid] = bo[tid]; sb1[tid] = b1[tid]; sW2[tid] = W2[tid]; sAcc[tid] = 0.f; }
    if (tid == 0) sb2 = b2[0];
    __syncthreads();

    int warp = tid >> 5, lane = tid & 31;
    int row = blockIdx.x * 8 + warp;        // < 262144 ; row = tb*N + n
    int tb = row >> 14;
    int n  = row & 16383;
    int kall = n >> 12;

    float2 yo2 = ((const float2*)g_yo)[(size_t)row * 32 + lane];
    sY[warp][2*lane]   = yo2.x;
    sY[warp][2*lane+1] = yo2.y;
    __syncwarp();

    float cn = (float)g_cnt[n];
    float invnnz = 1.f / nnz[n];
    int e0 = 2 * lane;

    float a0 = cn * sbo[e0], a1 = cn * sbo[e0 + 1];
    #pragma unroll
    for (int j = 0; j < 64; j++) {
        float yj = sY[warp][j];
        a0 += yj * sWo[j*64 + e0];
        a1 += yj * sWo[j*64 + e0 + 1];
    }
    a0 *= invnnz; a1 *= invnnz;

    atomicAdd(&sAcc[e0], a0);
    atomicAdd(&sAcc[e0 + 1], a1);

    sZ[warp][e0] = a0; sZ[warp][e0 + 1] = a1;
    if (lane < 4) sZ[warp][64 + lane] = extra[(tb * KALLc + kall) * 4 + lane];
    __syncwarp();

    float m0 = sb1[e0], m1 = sb1[e0 + 1];
    #pragma unroll
    for (int j = 0; j < 68; j++) {
        float zj = sZ[warp][j];
        m0 += zj * sW1[j*64 + e0];
        m1 += zj * sW1[j*64 + e0 + 1];
    }
    m0 = fmaxf(m0, 0.f); m1 = fmaxf(m1, 0.f);
    float part = m0 * sW2[e0] + m1 * sW2[e0 + 1];
    #pragma unroll
    for (int off = 16; off; off >>= 1) part += __shfl_xor_sync(0xffffffffu, part, off);
    if (lane == 0) logit_out[row] = part + sb2;

    __syncthreads();
    if (tid < 64) atomicAdd(&g_yg[(tb * KALLc + kall) * 64 + tid], sAcc[tid]);
}

// ---------------------------------------------------------------------------
// Value head: value[t,b] = sum_k ( [mean_n(y), extra] @ Wv1 + bv1 )
// ---------------------------------------------------------------------------
__global__ void k_value(const float* __restrict__ extra,
                        const float* __restrict__ Wv1, const float* __restrict__ bv1,
                        float* __restrict__ val_out)
{
    __shared__ float sv[64];
    int tid = threadIdx.x;                  // 64 threads = (tb, k)
    const float* yg = g_yg + tid * 64;
    float acc = bv1[0];
    const float invN0 = 1.f / (float)N0c;
    #pragma unroll
    for (int j = 0; j < 64; j++) acc += (yg[j] * invN0) * Wv1[j];
    #pragma unroll
    for (int d = 0; d < 4; d++) acc += extra[tid * 4 + d] * Wv1[64 + d];
    sv[tid] = acc;
    __syncthreads();
    if (tid < 16)
        val_out[tid] = sv[tid*4] + sv[tid*4+1] + sv[tid*4+2] + sv[tid*4+3];
}

// ---------------------------------------------------------------------------
extern "C" void kernel_launch(void* const* d_in, const int* in_sizes, int n_in,
                              void* d_out, int out_size)
{
    const float* h0       = (const float*)d_in[0];
    const float* h_global = (const float*)d_in[1];
    const float* x        = (const float*)d_in[2];
    const float* extra    = (const float*)d_in[3];
    const uint32_t* dones = (const uint32_t*)d_in[4];
    const int*   indices  = (const int*)d_in[5];
    const float* nnz      = (const float*)d_in[6];
    const float* Wi  = (const float*)d_in[7];
    const float* bi  = (const float*)d_in[8];
    const float* Wh  = (const float*)d_in[9];
    const float* bhn = (const float*)d_in[10];
    const float* Wq  = (const float*)d_in[11];
    const float* bq  = (const float*)d_in[12];
    const float* Wk  = (const float*)d_in[13];
    const float* bk  = (const float*)d_in[14];
    const float* Wv  = (const float*)d_in[15];
    const float* bv  = (const float*)d_in[16];
    const float* Wo  = (const float*)d_in[17];
    const float* bo  = (const float*)d_in[18];
    const float* W1  = (const float*)d_in[19];
    const float* b1  = (const float*)d_in[20];
    const float* W2  = (const float*)d_in[21];
    const float* b2  = (const float*)d_in[22];
    const float* Wv1 = (const float*)d_in[23];
    const float* bv1 = (const float*)d_in[24];

    float* out       = (float*)d_out;
    float* out_hfin  = out;
    float* out_hg    = out + OFF_HG;
    float* out_logit = out + OFF_LOGIT;
    float* out_val   = out + OFF_VAL;

    void *yo_ptr, *yg_ptr, *cnt_ptr;
    cudaGetSymbolAddress(&yo_ptr,  g_yo);
    cudaGetSymbolAddress(&yg_ptr,  g_yg);
    cudaGetSymbolAddress(&cnt_ptr, g_cnt);
    cudaMemsetAsync(yo_ptr,  0, sizeof(float) * (size_t)TBNc * Hh, 0);
    cudaMemsetAsync(yg_ptr,  0, sizeof(float) * TBc * KALLc * Hh, 0);
    cudaMemsetAsync(cnt_ptr, 0, sizeof(int) * Nn, 0);

    cudaMemcpyAsync(out_hg, h_global, 1024 * sizeof(float), cudaMemcpyDeviceToDevice, 0);

    int smem_gru = (12288 + 768 + 12288 + 192 + 192 + 64) * 4;   // 103168 B
    cudaFuncSetAttribute(k_gru_qkv, cudaFuncAttributeMaxDynamicSharedMemorySize, smem_gru);

    k_count<<<(Ff * ORD + 255) / 256, 256>>>(indices);
    k_gru_qkv<<<BNc / 128, 128, smem_gru>>>(h0, x, dones, Wi, bi, Wh, bhn,
                                            Wq, bq, Wk, bk, Wv, bv, out_hfin);
    k_attn<<<TBc * Ff / 8, 256>>>(indices);
    k_post<<<TBNc / 8, 256>>>(nnz, extra, Wo, bo, W1, b1, W2, b2, out_logit);
    k_value<<<1, 64>>>(extra, Wv1, bv1, out_val);
}